// round 3
// baseline (speedup 1.0000x reference)
#include <cuda_runtime.h>
#include <cuda_bf16.h>

#define NPTS 8192
#define NB   2
#define TPB  256

__device__ __forceinline__ float aniso_one(
    float px, float py, float pz,
    float pix, float piy, float piz,
    float tx, float ty, float tz,
    float pdself, float sqi, float tn2m2,
    float alpha, float beta)
{
    // along = (p_i . t_i) - (p_j . t_i)
    float pjt   = fmaf(px, tx, fmaf(py, ty, pz * tz));
    float along = pdself - pjt;
    float a2    = along * along;
    // gram = p_i . p_j ; sq_j = ||p_j||^2
    float gram  = fmaf(px, pix, fmaf(py, piy, pz * piz));
    float sqj   = fmaf(px, px, fmaf(py, py, pz * pz));
    float sqd   = sqi + sqj - 2.0f * gram;
    float ns    = fmaxf(fmaf(a2, tn2m2, sqd), 0.0f);
    return fmaf(alpha, ns, beta * a2);
}

__global__ void __launch_bounds__(TPB, 8)
aniso_kernel(const float* __restrict__ points,
             const float* __restrict__ pdir,
             const float* __restrict__ lin,
             float* __restrict__ out)
{
    const int i = blockIdx.x;
    const int b = blockIdx.y;

    const float* __restrict__ pb = points + (size_t)b * NPTS * 3;
    const float* __restrict__ pi = pb + (size_t)i * 3;
    const float* __restrict__ ti = pdir + ((size_t)b * NPTS + (size_t)i) * 3;

    const float pix = pi[0], piy = pi[1], piz = pi[2];
    const float tx  = ti[0], ty  = ti[1], tz  = ti[2];

    const float pdself = fmaf(pix, tx, fmaf(piy, ty, piz * tz));
    const float sqi    = fmaf(pix, pix, fmaf(piy, piy, piz * piz));
    const float tn2m2  = fmaf(tx, tx, fmaf(ty, ty, tz * tz)) - 2.0f;

    const float l     = lin[(size_t)b * NPTS + (size_t)i];
    const float alpha = 2.0f * (1.0f + l);
    const float beta  = 0.5f * (1.0f - l);

    float4* __restrict__ out4 = (float4*)(out + ((size_t)b * NPTS + (size_t)i) * NPTS);
    const float4* __restrict__ pts4 = (const float4*)pb;

    // N/4 = 2048 float4 outputs per row; 256 threads -> 8 iterations each.
    #pragma unroll
    for (int it = 0; it < (NPTS / 4) / TPB; ++it) {
        const int jv = it * TPB + threadIdx.x;
        // 4 consecutive points = 48 bytes = 3 aligned float4 loads
        const float4 A = pts4[jv * 3 + 0];
        const float4 C = pts4[jv * 3 + 1];
        const float4 D = pts4[jv * 3 + 2];
        // point j0: (A.x,A.y,A.z)  j1: (A.w,C.x,C.y)
        // point j2: (C.z,C.w,D.x)  j3: (D.y,D.z,D.w)
        float4 r;
        r.x = aniso_one(A.x, A.y, A.z, pix, piy, piz, tx, ty, tz,
                        pdself, sqi, tn2m2, alpha, beta);
        r.y = aniso_one(A.w, C.x, C.y, pix, piy, piz, tx, ty, tz,
                        pdself, sqi, tn2m2, alpha, beta);
        r.z = aniso_one(C.z, C.w, D.x, pix, piy, piz, tx, ty, tz,
                        pdself, sqi, tn2m2, alpha, beta);
        r.w = aniso_one(D.y, D.z, D.w, pix, piy, piz, tx, ty, tz,
                        pdself, sqi, tn2m2, alpha, beta);
        out4[jv] = r;
    }
}

extern "C" void kernel_launch(void* const* d_in, const int* in_sizes, int n_in,
                              void* d_out, int out_size)
{
    const float* points = (const float*)d_in[0];
    const float* pdir   = (const float*)d_in[1];
    const float* lin    = (const float*)d_in[2];
    float* out          = (float*)d_out;

    dim3 grid(NPTS, NB);
    aniso_kernel<<<grid, TPB>>>(points, pdir, lin, out);
}

// round 4
// speedup vs baseline: 1.2185x; 1.2185x over previous
#include <cuda_runtime.h>
#include <cuda_bf16.h>

#define NPTS 8192
#define NB   2
#define TPB  256
#define IT   4   // i-rows per CTA

__global__ void __launch_bounds__(TPB, 2)
aniso_kernel(const float* __restrict__ points,
             const float* __restrict__ pdir,
             const float* __restrict__ lin,
             float* __restrict__ out)
{
    const int i0 = blockIdx.x * IT;
    const int b  = blockIdx.y;

    const float* __restrict__ pb = points + (size_t)b * NPTS * 3;

    // Per-row (i) constants, kept in registers.
    float pix[IT], piy[IT], piz[IT];
    float tx[IT],  ty[IT],  tz[IT];
    float cc[IT], s0[IT], k2[IT], al[IT], be[IT];

    #pragma unroll
    for (int r = 0; r < IT; ++r) {
        const float* pi = pb + (size_t)(i0 + r) * 3;
        const float* ti = pdir + ((size_t)b * NPTS + (size_t)(i0 + r)) * 3;
        pix[r] = pi[0]; piy[r] = pi[1]; piz[r] = pi[2];
        tx[r]  = ti[0]; ty[r]  = ti[1]; tz[r]  = ti[2];

        cc[r] = fmaf(pix[r], tx[r], fmaf(piy[r], ty[r], piz[r] * tz[r]));   // p_i . t_i
        s0[r] = fmaf(pix[r], pix[r], fmaf(piy[r], piy[r], piz[r] * piz[r])); // ||p_i||^2
        k2[r] = fmaf(tx[r], tx[r], fmaf(ty[r], ty[r], tz[r] * tz[r])) - 2.0f; // ||t||^2 - 2

        const float l = lin[(size_t)b * NPTS + (size_t)(i0 + r)];
        al[r] = 2.0f * (1.0f + l);
        be[r] = 0.5f * (1.0f - l);
    }

    const float4* __restrict__ pts4 = (const float4*)pb;
    float* __restrict__ outbase = out + ((size_t)b * NPTS + (size_t)i0) * NPTS;

    // 2048 float4 column-groups per row; 256 threads -> 8 iterations.
    #pragma unroll
    for (int itn = 0; itn < (NPTS / 4) / TPB; ++itn) {
        const int jv = itn * TPB + threadIdx.x;

        // 4 consecutive points = 48 B = 3 aligned float4 loads (L1-resident).
        const float4 A = pts4[jv * 3 + 0];
        const float4 C = pts4[jv * 3 + 1];
        const float4 D = pts4[jv * 3 + 2];

        const float px[4] = {A.x, A.w, C.z, D.y};
        const float py[4] = {A.y, C.x, C.w, D.z};
        const float pz[4] = {A.z, C.y, D.x, D.w};

        // ||p_j||^2 hoisted: computed once, reused by all IT rows.
        float sj[4];
        #pragma unroll
        for (int q = 0; q < 4; ++q)
            sj[q] = fmaf(px[q], px[q], fmaf(py[q], py[q], pz[q] * pz[q]));

        #pragma unroll
        for (int r = 0; r < IT; ++r) {
            float o[4];
            #pragma unroll
            for (int q = 0; q < 4; ++q) {
                float d     = fmaf(px[q], tx[r], fmaf(py[q], ty[r], pz[q] * tz[r])); // p_j . t_i
                float along = cc[r] - d;
                float a2    = along * along;
                float g     = fmaf(px[q], pix[r], fmaf(py[q], piy[r], pz[q] * piz[r])); // p_j . p_i
                float sqd   = fmaf(g, -2.0f, s0[r] + sj[q]);
                float ns    = fmaxf(fmaf(a2, k2[r], sqd), 0.0f);
                o[q] = fmaf(al[r], ns, be[r] * a2);
            }
            // Streaming 16B store; output row r of this i-block.
            __stcs((float4*)(outbase + (size_t)r * NPTS) + jv,
                   make_float4(o[0], o[1], o[2], o[3]));
        }
    }
}

extern "C" void kernel_launch(void* const* d_in, const int* in_sizes, int n_in,
                              void* d_out, int out_size)
{
    const float* points = (const float*)d_in[0];
    const float* pdir   = (const float*)d_in[1];
    const float* lin    = (const float*)d_in[2];
    float* out          = (float*)d_out;

    dim3 grid(NPTS / IT, NB);
    aniso_kernel<<<grid, TPB>>>(points, pdir, lin, out);
}